// round 4
// baseline (speedup 1.0000x reference)
#include <cuda_runtime.h>

#define BB    4
#define CC    256
#define HH    128
#define WW    256
#define NG    4
#define CG    64
#define TAPS  9
#define PADX  4
#define TW    64
#define EXT   (TW + TAPS - 1)   // 72
#define WSTR  76                // smem row stride
#define HWSZ  (HH * WW)
#define BUFSZ (CG * WSTR)       // 4864 floats = 19456 B (>= 18432 B s_part alias)

__global__ __launch_bounds__(256, 4)
void crestereo_corr_kernel(const float* __restrict__ left,
                           const float* __restrict__ right,
                           const float* __restrict__ flow,
                           float* __restrict__ out)
{
    __shared__ int   s_idx[4][EXT];
    __shared__ float s_wt[4][EXT];
    __shared__ int   s_perm[EXT];
    __shared__ __align__(16) float s_warp[BUFSZ];   // warped tile; later aliased as s_part

    const int tid = threadIdx.x;
    const int x0t = blockIdx.x * TW;
    const int y   = blockIdx.y;
    const int b   = blockIdx.z;

    // ---------------- Phase A: per-halo-column bilinear sample info ----------------
    if (tid < EXT) {
        int xo = x0t + tid - PADX;
        xo = max(0, min(WW - 1, xo));
        const float fx = flow[((size_t)(b * 2 + 0) * HH + y) * WW + xo];
        const float fy = flow[((size_t)(b * 2 + 1) * HH + y) * WW + xo];
        float cx = (float)xo + fx;
        float cy = (float)y + fy;
        float fx0 = floorf(cx), fy0 = floorf(cy);
        float ax = cx - fx0, ay = cy - fy0;
        int ix0 = (int)fx0, iy0 = (int)fy0;
        int ix1 = ix0 + 1, iy1 = iy0 + 1;
        float wx0 = 1.f - ax, wy0 = 1.f - ay;
        int cx0 = max(0, min(WW - 1, ix0));
        int cx1 = max(0, min(WW - 1, ix1));
        int cy0 = max(0, min(HH - 1, iy0));
        int cy1 = max(0, min(HH - 1, iy1));
        bool vx0 = (ix0 >= 0) && (ix0 <= WW - 1);
        bool vx1 = (ix1 >= 0) && (ix1 <= WW - 1);
        bool vy0 = (iy0 >= 0) && (iy0 <= HH - 1);
        bool vy1 = (iy1 >= 0) && (iy1 <= HH - 1);
        s_idx[0][tid] = cy0 * WW + cx0;
        s_idx[1][tid] = cy0 * WW + cx1;
        s_idx[2][tid] = cy1 * WW + cx0;
        s_idx[3][tid] = cy1 * WW + cx1;
        s_wt[0][tid] = (vx0 && vy0) ? wx0 * wy0 : 0.f;
        s_wt[1][tid] = (vx1 && vy0) ? ax  * wy0 : 0.f;
        s_wt[2][tid] = (vx0 && vy1) ? wx0 * ay  : 0.f;
        s_wt[3][tid] = (vx1 && vy1) ? ax  * ay  : 0.f;
    }
    __syncthreads();

    // ---- Rank-sort the 72 halo columns by corner-0 linear index (y-major) ----
    // Warp lanes then gather same-row, ascending-x addresses -> few sectors/LDG.
    if (tid < EXT) {
        const int k = s_idx[0][tid];
        int r = 0;
        #pragma unroll 8
        for (int j = 0; j < EXT; ++j) {
            int kj = s_idx[0][j];
            r += (kj < k) || (kj == k && j < tid);
        }
        s_perm[r] = tid;
    }
    __syncthreads();

    // -------- Per-thread gather assignment through the permutation --------
    // Main: sorted slot tid&63 -> column e_m; channels (tid>>6) + 4k, k=0..15
    // Extra: sorted slot 64+(tid&7) -> column e_x; channels (tid>>3) + 32m, m=0..1
    const int e_m  = s_perm[tid & 63];
    const int cb_m = tid >> 6;
    const int e_x  = s_perm[64 + (tid & 7)];
    const int cb_x = tid >> 3;

    const int   im0 = s_idx[0][e_m], im1 = s_idx[1][e_m], im2 = s_idx[2][e_m], im3 = s_idx[3][e_m];
    const float wm0 = s_wt[0][e_m],  wm1 = s_wt[1][e_m],  wm2 = s_wt[2][e_m],  wm3 = s_wt[3][e_m];
    const int   ie0 = s_idx[0][e_x], ie1 = s_idx[1][e_x], ie2 = s_idx[2][e_x], ie3 = s_idx[3][e_x];
    const float we0 = s_wt[0][e_x],  we1 = s_wt[1][e_x],  we2 = s_wt[2][e_x],  we3 = s_wt[3][e_x];

    const float* rbatch = right + (size_t)b * CC * HWSZ;

    const int slot   = tid & 15;   // owns out cols [slot*4, slot*4+4)
    const int cq     = tid >> 4;   // owns channels [cq*4, cq*4+4)
    const int xl     = slot * 4;
    const int warpid = tid >> 5;

    const float* lpb = left + ((size_t)(b * CC + cq * 4) * HH + y) * WW + x0t + xl;

    for (int g = 0; g < NG; ++g) {
        // ---------------- Phase B: bilinear gather, batched for MLP ----------------
        const float* rg = rbatch + (size_t)g * CG * HWSZ;

        // extra columns (8 LDGs in flight)
        {
            const float* q0 = rg + (size_t)cb_x * HWSZ;
            const float* q1 = q0 + (size_t)32 * HWSZ;
            float a0 = __ldg(q0 + ie0), a1 = __ldg(q0 + ie1), a2 = __ldg(q0 + ie2), a3 = __ldg(q0 + ie3);
            float b0 = __ldg(q1 + ie0), b1 = __ldg(q1 + ie1), b2 = __ldg(q1 + ie2), b3 = __ldg(q1 + ie3);
            s_warp[cb_x * WSTR + e_x]        = we0 * a0 + we1 * a1 + we2 * a2 + we3 * a3;
            s_warp[(cb_x + 32) * WSTR + e_x] = we0 * b0 + we1 * b1 + we2 * b2 + we3 * b3;
        }

        // main columns: 16 channels, in 4 chunks of 4 (16 LDGs in flight per chunk)
        const float* pm = rg + (size_t)cb_m * HWSZ;
        #pragma unroll
        for (int kk = 0; kk < 4; ++kk) {
            float v[4][4];
            #pragma unroll
            for (int j = 0; j < 4; ++j) {
                const float* pc = pm + (size_t)(4 * (4 * kk + j)) * HWSZ;
                v[j][0] = __ldg(pc + im0);
                v[j][1] = __ldg(pc + im1);
                v[j][2] = __ldg(pc + im2);
                v[j][3] = __ldg(pc + im3);
            }
            #pragma unroll
            for (int j = 0; j < 4; ++j) {
                s_warp[(cb_m + 4 * (4 * kk + j)) * WSTR + e_m] =
                    wm0 * v[j][0] + wm1 * v[j][1] + wm2 * v[j][2] + wm3 * v[j][3];
            }
        }

        // left loads issued before the barrier — complete during the wait
        const float* lp = lpb + (size_t)(g * CG) * HWSZ;
        float4 lv0 = *reinterpret_cast<const float4*>(lp);
        float4 lv1 = *reinterpret_cast<const float4*>(lp + HWSZ);
        float4 lv2 = *reinterpret_cast<const float4*>(lp + 2 * HWSZ);
        float4 lv3 = *reinterpret_cast<const float4*>(lp + 3 * HWSZ);

        __syncthreads();   // warp tile complete

        // ---------------- Phase C: 9-tap correlation (4 cols x 4 ch per thread) ----------------
        float acc[4][TAPS];
        #pragma unroll
        for (int xi = 0; xi < 4; ++xi)
            #pragma unroll
            for (int t = 0; t < TAPS; ++t) acc[xi][t] = 0.f;

        #pragma unroll
        for (int ci = 0; ci < 4; ++ci) {
            const float* wr = &s_warp[(cq * 4 + ci) * WSTR + xl];
            float4 w0 = *reinterpret_cast<const float4*>(wr);
            float4 w1 = *reinterpret_cast<const float4*>(wr + 4);
            float4 w2 = *reinterpret_cast<const float4*>(wr + 8);
            float win[12] = {w0.x, w0.y, w0.z, w0.w,
                             w1.x, w1.y, w1.z, w1.w,
                             w2.x, w2.y, w2.z, w2.w};
            float lvv[4];
            if (ci == 0) { lvv[0]=lv0.x; lvv[1]=lv0.y; lvv[2]=lv0.z; lvv[3]=lv0.w; }
            if (ci == 1) { lvv[0]=lv1.x; lvv[1]=lv1.y; lvv[2]=lv1.z; lvv[3]=lv1.w; }
            if (ci == 2) { lvv[0]=lv2.x; lvv[1]=lv2.y; lvv[2]=lv2.z; lvv[3]=lv2.w; }
            if (ci == 3) { lvv[0]=lv3.x; lvv[1]=lv3.y; lvv[2]=lv3.z; lvv[3]=lv3.w; }
            #pragma unroll
            for (int xi = 0; xi < 4; ++xi)
                #pragma unroll
                for (int t = 0; t < TAPS; ++t)
                    acc[xi][t] += lvv[xi] * win[xi + t];
        }

        // pair-reduce the two cq's sharing a warp
        #pragma unroll
        for (int xi = 0; xi < 4; ++xi)
            #pragma unroll
            for (int t = 0; t < TAPS; ++t)
                acc[xi][t] += __shfl_xor_sync(0xffffffffu, acc[xi][t], 16);

        __syncthreads();   // s_warp reads done -> safe to alias

        float* s_part = s_warp;   // 8*16*36 = 18432 B alias
        if ((tid & 16) == 0) {
            float* pp = &s_part[(warpid * 16 + slot) * 36];
            #pragma unroll
            for (int xi = 0; xi < 4; ++xi)
                #pragma unroll
                for (int t = 0; t < TAPS; ++t)
                    pp[xi * TAPS + t] = acc[xi][t];
        }
        __syncthreads();

        // ---------------- Reduce 8 partials + coalesced store ----------------
        float* ob = out + (((size_t)b * (NG * TAPS) + g * TAPS) * HH + y) * WW + x0t;
        #pragma unroll
        for (int r = 0; r < 3; ++r) {
            int j = tid + r * 256;
            if (r < 2 || tid < 64) {   // 576 = 2*256 + 64
                int x  = j & (TW - 1);
                int t  = j >> 6;
                int sl = x >> 2;
                int xi = x & 3;
                int k  = xi * TAPS + t;
                float s = 0.f;
                #pragma unroll
                for (int p = 0; p < 8; ++p)
                    s += s_part[(p * 16 + sl) * 36 + k];
                ob[(size_t)t * HH * WW + x] = s * (1.f / CG);
            }
        }
        __syncthreads();   // reduce reads done before next gather overwrites
    }
}

extern "C" void kernel_launch(void* const* d_in, const int* in_sizes, int n_in,
                              void* d_out, int out_size) {
    const float* left  = (const float*)d_in[0];
    const float* right = (const float*)d_in[1];
    const float* flow  = (const float*)d_in[2];
    float* out = (float*)d_out;
    dim3 grid(WW / TW, HH, BB);   // (4, 128, 4) = 2048 blocks
    crestereo_corr_kernel<<<grid, 256>>>(left, right, flow, out);
}

// round 6
// speedup vs baseline: 1.0877x; 1.0877x over previous
#include <cuda_runtime.h>

#define BB    4
#define CC    256
#define HH    128
#define WW    256
#define NG    4
#define CG    64
#define TAPS  9
#define PADX  4
#define TW    64
#define EXT   (TW + TAPS - 1)   // 72
#define WSTR  76                // smem row stride
#define HWSZ  (HH * WW)
#define BUFSZ (CG * WSTR)       // 4864 floats = 19456 B (>= 18432 B s_part alias)

__global__ __launch_bounds__(256, 4)
void crestereo_corr_kernel(const float* __restrict__ left,
                           const float* __restrict__ right,
                           const float* __restrict__ flow,
                           float* __restrict__ out)
{
    __shared__ int   s_idx[4][EXT];
    __shared__ float s_wt[4][EXT];
    __shared__ __align__(16) float s_warp[BUFSZ];   // warped tile; later aliased as s_part

    const int tid = threadIdx.x;
    const int x0t = blockIdx.x * TW;
    const int y   = blockIdx.y;
    const int b   = blockIdx.z;

    // ---------------- Phase A: per-halo-column bilinear sample info ----------------
    if (tid < EXT) {
        int xo = x0t + tid - PADX;
        xo = max(0, min(WW - 1, xo));
        const float fx = flow[((size_t)(b * 2 + 0) * HH + y) * WW + xo];
        const float fy = flow[((size_t)(b * 2 + 1) * HH + y) * WW + xo];
        float cx = (float)xo + fx;
        float cy = (float)y + fy;
        float fx0 = floorf(cx), fy0 = floorf(cy);
        float ax = cx - fx0, ay = cy - fy0;
        int ix0 = (int)fx0, iy0 = (int)fy0;
        int ix1 = ix0 + 1, iy1 = iy0 + 1;
        float wx0 = 1.f - ax, wy0 = 1.f - ay;
        int cx0 = max(0, min(WW - 1, ix0));
        int cx1 = max(0, min(WW - 1, ix1));
        int cy0 = max(0, min(HH - 1, iy0));
        int cy1 = max(0, min(HH - 1, iy1));
        bool vx0 = (ix0 >= 0) && (ix0 <= WW - 1);
        bool vx1 = (ix1 >= 0) && (ix1 <= WW - 1);
        bool vy0 = (iy0 >= 0) && (iy0 <= HH - 1);
        bool vy1 = (iy1 >= 0) && (iy1 <= HH - 1);
        s_idx[0][tid] = cy0 * WW + cx0;
        s_idx[1][tid] = cy0 * WW + cx1;
        s_idx[2][tid] = cy1 * WW + cx0;
        s_idx[3][tid] = cy1 * WW + cx1;
        s_wt[0][tid] = (vx0 && vy0) ? wx0 * wy0 : 0.f;
        s_wt[1][tid] = (vx1 && vy0) ? ax  * wy0 : 0.f;
        s_wt[2][tid] = (vx0 && vy1) ? wx0 * ay  : 0.f;
        s_wt[3][tid] = (vx1 && vy1) ? ax  * ay  : 0.f;
    }
    __syncthreads();

    // -------- Per-thread gather assignment (group-invariant; weights in registers) --------
    const int e_m  = tid & 63;
    const int cb_m = tid >> 6;
    const int e_x  = 64 + (tid & 7);
    const int cb_x = tid >> 3;

    const int   im0 = s_idx[0][e_m], im1 = s_idx[1][e_m], im2 = s_idx[2][e_m], im3 = s_idx[3][e_m];
    const float wm0 = s_wt[0][e_m],  wm1 = s_wt[1][e_m],  wm2 = s_wt[2][e_m],  wm3 = s_wt[3][e_m];
    const int   ie0 = s_idx[0][e_x], ie1 = s_idx[1][e_x], ie2 = s_idx[2][e_x], ie3 = s_idx[3][e_x];
    const float we0 = s_wt[0][e_x],  we1 = s_wt[1][e_x],  we2 = s_wt[2][e_x],  we3 = s_wt[3][e_x];

    const float* rbatch = right + (size_t)b * CC * HWSZ;

    const int slot   = tid & 15;   // owns out cols [slot*4, slot*4+4)
    const int cq     = tid >> 4;   // owns channels [cq*4, cq*4+4)
    const int xl     = slot * 4;
    const int warpid = tid >> 5;

    const float* lpb = left + ((size_t)(b * CC + cq * 4) * HH + y) * WW + x0t + xl;

    // reduce-phase thread mapping (tid < 144): (sl, t) quad of x-outputs
    const int r_sl = tid & 15;
    const int r_t  = tid >> 4;

    for (int g = 0; g < NG; ++g) {
        // ---------------- Phase B: bilinear gather, batched for MLP ----------------
        const float* rg = rbatch + (size_t)g * CG * HWSZ;

        // extra columns (8 LDGs in flight)
        {
            const float* q0 = rg + (size_t)cb_x * HWSZ;
            const float* q1 = q0 + (size_t)32 * HWSZ;
            float a0 = __ldg(q0 + ie0), a1 = __ldg(q0 + ie1), a2 = __ldg(q0 + ie2), a3 = __ldg(q0 + ie3);
            float b0 = __ldg(q1 + ie0), b1 = __ldg(q1 + ie1), b2 = __ldg(q1 + ie2), b3 = __ldg(q1 + ie3);
            s_warp[cb_x * WSTR + e_x]        = we0 * a0 + we1 * a1 + we2 * a2 + we3 * a3;
            s_warp[(cb_x + 32) * WSTR + e_x] = we0 * b0 + we1 * b1 + we2 * b2 + we3 * b3;
        }

        // main columns: 16 channels, in 4 chunks of 4 (16 LDGs in flight per chunk)
        const float* pm = rg + (size_t)cb_m * HWSZ;
        #pragma unroll
        for (int kk = 0; kk < 4; ++kk) {
            float v[4][4];
            #pragma unroll
            for (int j = 0; j < 4; ++j) {
                const float* pc = pm + (size_t)(4 * (4 * kk + j)) * HWSZ;
                v[j][0] = __ldg(pc + im0);
                v[j][1] = __ldg(pc + im1);
                v[j][2] = __ldg(pc + im2);
                v[j][3] = __ldg(pc + im3);
            }
            #pragma unroll
            for (int j = 0; j < 4; ++j) {
                s_warp[(cb_m + 4 * (4 * kk + j)) * WSTR + e_m] =
                    wm0 * v[j][0] + wm1 * v[j][1] + wm2 * v[j][2] + wm3 * v[j][3];
            }
        }

        // left loads issued before the barrier — complete during the wait
        const float* lp = lpb + (size_t)(g * CG) * HWSZ;
        float4 lv0 = *reinterpret_cast<const float4*>(lp);
        float4 lv1 = *reinterpret_cast<const float4*>(lp + HWSZ);
        float4 lv2 = *reinterpret_cast<const float4*>(lp + 2 * HWSZ);
        float4 lv3 = *reinterpret_cast<const float4*>(lp + 3 * HWSZ);

        __syncthreads();   // warp tile complete

        // ---------------- Phase C: 9-tap correlation; acc4[t] = (xi=0..3) ----------------
        float4 acc4[TAPS];
        #pragma unroll
        for (int t = 0; t < TAPS; ++t) acc4[t] = make_float4(0.f, 0.f, 0.f, 0.f);

        #pragma unroll
        for (int ci = 0; ci < 4; ++ci) {
            const float* wr = &s_warp[(cq * 4 + ci) * WSTR + xl];
            float4 w0 = *reinterpret_cast<const float4*>(wr);
            float4 w1 = *reinterpret_cast<const float4*>(wr + 4);
            float4 w2 = *reinterpret_cast<const float4*>(wr + 8);
            float win[12] = {w0.x, w0.y, w0.z, w0.w,
                             w1.x, w1.y, w1.z, w1.w,
                             w2.x, w2.y, w2.z, w2.w};
            float lvv[4];
            if (ci == 0) { lvv[0]=lv0.x; lvv[1]=lv0.y; lvv[2]=lv0.z; lvv[3]=lv0.w; }
            if (ci == 1) { lvv[0]=lv1.x; lvv[1]=lv1.y; lvv[2]=lv1.z; lvv[3]=lv1.w; }
            if (ci == 2) { lvv[0]=lv2.x; lvv[1]=lv2.y; lvv[2]=lv2.z; lvv[3]=lv2.w; }
            if (ci == 3) { lvv[0]=lv3.x; lvv[1]=lv3.y; lvv[2]=lv3.z; lvv[3]=lv3.w; }
            #pragma unroll
            for (int t = 0; t < TAPS; ++t) {
                acc4[t].x += lvv[0] * win[0 + t];
                acc4[t].y += lvv[1] * win[1 + t];
                acc4[t].z += lvv[2] * win[2 + t];
                acc4[t].w += lvv[3] * win[3 + t];
            }
        }

        // pair-reduce the two cq's sharing a warp
        #pragma unroll
        for (int t = 0; t < TAPS; ++t) {
            acc4[t].x += __shfl_xor_sync(0xffffffffu, acc4[t].x, 16);
            acc4[t].y += __shfl_xor_sync(0xffffffffu, acc4[t].y, 16);
            acc4[t].z += __shfl_xor_sync(0xffffffffu, acc4[t].z, 16);
            acc4[t].w += __shfl_xor_sync(0xffffffffu, acc4[t].w, 16);
        }

        __syncthreads();   // s_warp reads done -> safe to alias

        // s_part rows: (p*16 + slot) * 36 floats; each row = 9 float4 (t-major, xi inner)
        float* s_part = s_warp;
        if ((tid & 16) == 0) {
            float* pp = &s_part[(warpid * 16 + slot) * 36];
            #pragma unroll
            for (int t = 0; t < TAPS; ++t)
                *reinterpret_cast<float4*>(pp + 4 * t) = acc4[t];
        }
        __syncthreads();

        // ---------------- Reduce 8 partials (vectorized) + STG.128 ----------------
        if (tid < 16 * TAPS) {
            float4 s = make_float4(0.f, 0.f, 0.f, 0.f);
            const float* pp = &s_part[r_sl * 36 + 4 * r_t];
            #pragma unroll
            for (int p = 0; p < 8; ++p) {
                float4 v = *reinterpret_cast<const float4*>(pp + p * (16 * 36));
                s.x += v.x; s.y += v.y; s.z += v.z; s.w += v.w;
            }
            s.x *= (1.f / CG); s.y *= (1.f / CG); s.z *= (1.f / CG); s.w *= (1.f / CG);
            float* op = out + (((size_t)b * (NG * TAPS) + g * TAPS + r_t) * HH + y) * WW + x0t + 4 * r_sl;
            *reinterpret_cast<float4*>(op) = s;
        }
        __syncthreads();   // reduce reads done before next gather overwrites
    }
}

extern "C" void kernel_launch(void* const* d_in, const int* in_sizes, int n_in,
                              void* d_out, int out_size) {
    const float* left  = (const float*)d_in[0];
    const float* right = (const float*)d_in[1];
    const float* flow  = (const float*)d_in[2];
    float* out = (float*)d_out;
    dim3 grid(WW / TW, HH, BB);   // (4, 128, 4) = 2048 blocks
    crestereo_corr_kernel<<<grid, 256>>>(left, right, flow, out);
}